// round 5
// baseline (speedup 1.0000x reference)
#include <cuda_runtime.h>
#include <cstdint>

#define N_NODES 100000
#define N_EDGES 1600000
#define IN_CH   128
#define HIDDEN  64
#define NCLS    40

#define N_TILES 782            // ceil(100000/128) gemm1 row tiles
#define NB_DEG  1563           // ceil(1.6M / (256*4))
#define EDGE_T  (NB_DEG * 256) // threads per edge phase

// ---------------- scratch (device globals; no allocation allowed) ----------
__device__ int   g_is64;
__device__ int   g_deg[N_NODES];
__device__ int   g_off[N_NODES + 1];
__device__ int   g_cur[N_NODES];
__device__ float g_dinv[N_NODES];
__device__ int   g_bsum[128];
__device__ int   g_boff[128];
__device__ int2  g_adj[N_EDGES];                     // (src, norm-as-bits), grouped by dst
__device__ float g_hw  [(size_t)N_NODES * HIDDEN];   // X @ W1
__device__ float g_agg1[(size_t)N_NODES * HIDDEN];   // layer1 aggregated (pre-relu)
__device__ float g_h2w [(size_t)N_NODES * NCLS];     // relu(agg1) @ W2

// ---------------- packed f32x2 helpers --------------------------------------
__device__ __forceinline__ unsigned long long ffma2(unsigned long long a,
                                                    unsigned long long b,
                                                    unsigned long long c) {
    unsigned long long d;
    asm("fma.rn.f32x2 %0, %1, %2, %3;" : "=l"(d) : "l"(a), "l"(b), "l"(c));
    return d;
}
__device__ __forceinline__ unsigned long long pack2(float a) {
    unsigned long long d;
    asm("mov.b64 %0, {%1, %1};" : "=l"(d) : "f"(a));
    return d;
}

// ---------------- gemm1 tile: 128 rows x 64 cols, K=128, 256 threads -------
// smem: sA[128][132] + sW[128][64]  = 100352 bytes
__device__ __forceinline__ void dev_gemm1(const float* __restrict__ A,
                                          const float* __restrict__ W,
                                          float* __restrict__ C,
                                          int rowbase, float* smem) {
    constexpr int KDIM = IN_CH, NDIM = HIDDEN, ROWS = 128, NT = 256;
    constexpr int PITCH = KDIM + 4;
    float* sA = smem;
    float* sW = smem + ROWS * PITCH;
    const int tid = threadIdx.x;

    for (int v = tid; v < KDIM * NDIM / 4; v += NT)
        ((float4*)sW)[v] = ((const float4*)W)[v];

    constexpr int KC4 = KDIM / 4;
    for (int v = tid; v < ROWS * KC4; v += NT) {
        int r  = v / KC4;
        int kc = (v - r * KC4) * 4;
        int row = rowbase + r;
        float4 a = make_float4(0.f, 0.f, 0.f, 0.f);
        if (row < N_NODES) a = *(const float4*)(A + (size_t)row * KDIM + kc);
        *(float4*)(sA + r * PITCH + kc) = a;
    }
    __syncthreads();

    const int ty = tid / 8, tx = tid & 7;   // 32 x 8
    unsigned long long acc[4][4];
#pragma unroll
    for (int i = 0; i < 4; i++)
#pragma unroll
        for (int j = 0; j < 4; j++) acc[i][j] = 0ull;

#pragma unroll 4
    for (int k = 0; k < KDIM; k++) {
        ulonglong2 b01 = *(const ulonglong2*)(sW + k * NDIM + 8 * tx);
        ulonglong2 b23 = *(const ulonglong2*)(sW + k * NDIM + 8 * tx + 4);
#pragma unroll
        for (int i = 0; i < 4; i++) {
            unsigned long long pa = pack2(sA[(4 * ty + i) * PITCH + k]);
            acc[i][0] = ffma2(pa, b01.x, acc[i][0]);
            acc[i][1] = ffma2(pa, b01.y, acc[i][1]);
            acc[i][2] = ffma2(pa, b23.x, acc[i][2]);
            acc[i][3] = ffma2(pa, b23.y, acc[i][3]);
        }
    }

#pragma unroll
    for (int i = 0; i < 4; i++) {
        int row = rowbase + 4 * ty + i;
        if (row < N_NODES) {
            ulonglong2* p = (ulonglong2*)(C + (size_t)row * NDIM + 8 * tx);
            p[0] = make_ulonglong2(acc[i][0], acc[i][1]);
            p[1] = make_ulonglong2(acc[i][2], acc[i][3]);
        }
    }
}

// ---------------- preprocessing phases (device functions) ------------------
__device__ __forceinline__ void dev_prep(const int* __restrict__ w, int obid) {
    int i = obid * 256 + threadIdx.x;
    if (i < N_NODES) g_deg[i] = 0;
    if (obid == 0) {  // detect index dtype: int64 has zero odd int32 words
        __shared__ int acc;
        if (threadIdx.x == 0) acc = 0;
        __syncthreads();
        int v = 0;
        for (int j = threadIdx.x; j < 4096; j += 256) v |= w[2 * j + 1];
        atomicOr(&acc, v);
        __syncthreads();
        if (threadIdx.x == 0) g_is64 = (acc == 0) ? 1 : 0;
    }
}

__device__ __forceinline__ void dev_deg(const int* __restrict__ w, int obid) {
    int idx = obid * 256 + threadIdx.x;
    int is64 = g_is64;
#pragma unroll
    for (int j = 0; j < 4; j++) {
        int e = idx + j * EDGE_T;
        if (e < N_EDGES) {
            int d = is64 ? w[2 * (N_EDGES + e)] : w[N_EDGES + e];
            if ((unsigned)d >= N_NODES) d = 0;
            atomicAdd(&g_deg[d], 1);
        }
    }
}

#define SCAN_NB  128
#define SCAN_TPB 256
#define SCAN_PER 4        // 128*256*4 = 131072 >= N_NODES

__device__ __forceinline__ void dev_scanA(int obid, int* red) {
    int t = threadIdx.x;
    int base = (obid * SCAN_TPB + t) * SCAN_PER;
    int s = 0;
#pragma unroll
    for (int j = 0; j < SCAN_PER; j++) {
        int i = base + j;
        if (i < N_NODES) s += g_deg[i];
    }
    red[t] = s;
    __syncthreads();
    for (int o = SCAN_TPB / 2; o > 0; o >>= 1) {
        if (t < o) red[t] += red[t + o];
        __syncthreads();
    }
    if (t == 0) g_bsum[obid] = red[0];
}

__device__ __forceinline__ void dev_scanB(int* p) {
    int t = threadIdx.x;
    if (t < SCAN_NB) p[t] = g_bsum[t];
    __syncthreads();
    for (int o = 1; o < SCAN_NB; o <<= 1) {
        int v = (t >= o && t < SCAN_NB) ? p[t - o] : 0;
        __syncthreads();
        if (t < SCAN_NB) p[t] += v;
        __syncthreads();
    }
    if (t < SCAN_NB) g_boff[t] = (t > 0) ? p[t - 1] : 0;
    if (t == SCAN_NB - 1) g_off[N_NODES] = p[t];
}

__device__ __forceinline__ void dev_scanC(int obid, int* p) {
    int t = threadIdx.x;
    int base = (obid * SCAN_TPB + t) * SCAN_PER;
    int loc[SCAN_PER];
    int s = 0;
#pragma unroll
    for (int j = 0; j < SCAN_PER; j++) {
        int i = base + j;
        int d = (i < N_NODES) ? g_deg[i] : 0;
        loc[j] = s;
        s += d;
    }
    p[t] = s;
    __syncthreads();
    for (int o = 1; o < SCAN_TPB; o <<= 1) {
        int v = (t >= o) ? p[t - o] : 0;
        __syncthreads();
        p[t] += v;
        __syncthreads();
    }
    int pre = g_boff[obid] + ((t > 0) ? p[t - 1] : 0);
#pragma unroll
    for (int j = 0; j < SCAN_PER; j++) {
        int i = base + j;
        if (i < N_NODES) {
            int o = pre + loc[j];
            g_off[i] = o;
            g_cur[i] = o;
            g_dinv[i] = rsqrtf((float)(g_deg[i] + 1));  // +1 self loop
        }
    }
}

__device__ __forceinline__ void dev_fill(const int* __restrict__ w, int obid) {
    int idx = obid * 256 + threadIdx.x;
    int is64 = g_is64;
#pragma unroll
    for (int j = 0; j < 4; j++) {
        int e = idx + j * EDGE_T;
        if (e < N_EDGES) {
            int s, d;
            if (is64) { s = w[2 * e]; d = w[2 * (N_EDGES + e)]; }
            else      { s = w[e];     d = w[N_EDGES + e]; }
            if ((unsigned)s >= N_NODES) s = 0;
            if ((unsigned)d >= N_NODES) d = 0;
            int pos = atomicAdd(&g_cur[d], 1);
            g_adj[pos] = make_int2(s, __float_as_int(g_dinv[s] * g_dinv[d]));
        }
    }
}

// ---------------- merged launches: gemm1 tiles + one preprocessing phase ---
#define P_PREP  0
#define P_DEG   1
#define P_SCANA 2
#define P_SCANB 3
#define P_SCANC 4
#define P_FILL  5

template<int PHASE>
__global__ void merged_kernel(const float* __restrict__ x,
                              const float* __restrict__ W1,
                              float* __restrict__ hw,
                              const int* __restrict__ ei,
                              int ngemm, int tile_off) {
    extern __shared__ float smem[];
    int bid = blockIdx.x;
    if (bid < ngemm) {
        dev_gemm1(x, W1, hw, (tile_off + bid) * 128, smem);
        return;
    }
    int obid = bid - ngemm;
    if (PHASE == P_PREP)  dev_prep(ei, obid);
    if (PHASE == P_DEG)   dev_deg(ei, obid);
    if (PHASE == P_SCANA) dev_scanA(obid, (int*)smem);
    if (PHASE == P_SCANB) dev_scanB((int*)smem);
    if (PHASE == P_SCANC) dev_scanC(obid, (int*)smem);
    if (PHASE == P_FILL)  dev_fill(ei, obid);
}

// ---------------- GEMM2: C[M,40] = relu(A[M,64]) * W[64,40] ----------------
template<int KDIM, int NDIM, int ROWS>
__global__ void gemm2_kernel(const float* __restrict__ A,
                             const float* __restrict__ W,
                             float* __restrict__ C, int M) {
    constexpr int TX    = NDIM / 8;     // 5
    constexpr int TY    = ROWS / 4;     // 32
    constexpr int NT    = TX * TY;      // 160
    constexpr int PITCH = KDIM + 4;
    extern __shared__ float smem[];
    float* sA = smem;
    float* sW = smem + ROWS * PITCH;

    const int tid     = threadIdx.x;
    const int rowbase = blockIdx.x * ROWS;

    for (int v = tid; v < KDIM * NDIM / 4; v += NT)
        ((float4*)sW)[v] = ((const float4*)W)[v];

    constexpr int KC4 = KDIM / 4;
    for (int v = tid; v < ROWS * KC4; v += NT) {
        int r  = v / KC4;
        int kc = (v - r * KC4) * 4;
        int row = rowbase + r;
        float4 a = make_float4(0.f, 0.f, 0.f, 0.f);
        if (row < M) a = *(const float4*)(A + (size_t)row * KDIM + kc);
        a.x = fmaxf(a.x, 0.f); a.y = fmaxf(a.y, 0.f);
        a.z = fmaxf(a.z, 0.f); a.w = fmaxf(a.w, 0.f);
        *(float4*)(sA + r * PITCH + kc) = a;
    }
    __syncthreads();

    const int ty = tid / TX, tx = tid - (tid / TX) * TX;
    unsigned long long acc[4][4];
#pragma unroll
    for (int i = 0; i < 4; i++)
#pragma unroll
        for (int j = 0; j < 4; j++) acc[i][j] = 0ull;

#pragma unroll 4
    for (int k = 0; k < KDIM; k++) {
        ulonglong2 b01 = *(const ulonglong2*)(sW + k * NDIM + 8 * tx);
        ulonglong2 b23 = *(const ulonglong2*)(sW + k * NDIM + 8 * tx + 4);
#pragma unroll
        for (int i = 0; i < 4; i++) {
            unsigned long long pa = pack2(sA[(4 * ty + i) * PITCH + k]);
            acc[i][0] = ffma2(pa, b01.x, acc[i][0]);
            acc[i][1] = ffma2(pa, b01.y, acc[i][1]);
            acc[i][2] = ffma2(pa, b23.x, acc[i][2]);
            acc[i][3] = ffma2(pa, b23.y, acc[i][3]);
        }
    }

#pragma unroll
    for (int i = 0; i < 4; i++) {
        int row = rowbase + 4 * ty + i;
        if (row < M) {
            ulonglong2* p = (ulonglong2*)(C + (size_t)row * NDIM + 8 * tx);
            p[0] = make_ulonglong2(acc[i][0], acc[i][1]);
            p[1] = make_ulonglong2(acc[i][2], acc[i][3]);
        }
    }
}

// ---------------- CSR aggregation with adj prefetch -------------------------
// out[i] = bias + dinv_i^2*feat[i] + sum_j norm_ij*feat[src_j]
template<int CH>
__global__ void aggregate_kernel(const float* __restrict__ feat,
                                 const float* __restrict__ bias,
                                 float* __restrict__ out) {
    constexpr int V4 = CH / 4;       // 16 (CH=64) or 10 (CH=40)
    constexpr int EP = 32 / V4;      // 2 or 3
    int node = (blockIdx.x * blockDim.x + threadIdx.x) >> 5;
    if (node >= N_NODES) return;
    int lane = threadIdx.x & 31;
    int eg = lane / V4;              // edge group
    int c  = lane - eg * V4;         // float4 index within row
    bool act = eg < EP;

    const int beg = g_off[node];
    const int end = g_off[node + 1];

    float4 acc = make_float4(0.f, 0.f, 0.f, 0.f);
    if (eg == 0) {                   // self-loop + bias in group 0 only
        float dv = g_dinv[node];
        float s  = dv * dv;
        float4 f  = ((const float4*)(feat + (size_t)node * CH))[c];
        float4 bb = ((const float4*)bias)[c];
        acc.x = fmaf(s, f.x, bb.x);
        acc.y = fmaf(s, f.y, bb.y);
        acc.z = fmaf(s, f.z, bb.z);
        acc.w = fmaf(s, f.w, bb.w);
    }

    // software-pipelined edge loop; dummy entries carry norm=0 (src=0 safe)
    int2 p = make_int2(0, 0);
    if (act && beg + eg < end) p = g_adj[beg + eg];
    for (int k = beg; k < end; k += EP) {
        int kn = k + EP;
        int2 pn = make_int2(0, 0);
        if (act && kn + eg < end) pn = g_adj[kn + eg];
        float nrm = __int_as_float(p.y);
        float4 v = ((const float4*)(feat + (size_t)p.x * CH))[c];
        acc.x = fmaf(nrm, v.x, acc.x);
        acc.y = fmaf(nrm, v.y, acc.y);
        acc.z = fmaf(nrm, v.z, acc.z);
        acc.w = fmaf(nrm, v.w, acc.w);
        p = pn;
    }

    // reduce groups 1..EP-1 into group 0 (shfls read pre-update values)
    const unsigned m = 0xffffffffu;
    float x1 = __shfl_down_sync(m, acc.x, V4);
    float y1 = __shfl_down_sync(m, acc.y, V4);
    float z1 = __shfl_down_sync(m, acc.z, V4);
    float w1 = __shfl_down_sync(m, acc.w, V4);
    if (EP > 2) {
        float x2 = __shfl_down_sync(m, acc.x, 2 * V4);
        float y2 = __shfl_down_sync(m, acc.y, 2 * V4);
        float z2 = __shfl_down_sync(m, acc.z, 2 * V4);
        float w2 = __shfl_down_sync(m, acc.w, 2 * V4);
        x1 += x2; y1 += y2; z1 += z2; w1 += w2;
    }
    acc.x += x1; acc.y += y1; acc.z += z1; acc.w += w1;

    if (eg == 0)
        ((float4*)(out + (size_t)node * CH))[c] = acc;
}

// ---------------- launch ----------------------------------------------------
extern "C" void kernel_launch(void* const* d_in, const int* in_sizes, int n_in,
                              void* d_out, int out_size) {
    const float* x  = (const float*)d_in[0];
    const int*   ei = (const int*)d_in[1];      // int32 words of edge_index (either dtype)
    const float* W1 = (const float*)d_in[2];
    const float* b1 = (const float*)d_in[3];
    const float* W2 = (const float*)d_in[4];
    const float* b2 = (const float*)d_in[5];
    float*       out = (float*)d_out;

    void *hw_p, *agg1_p, *h2w_p;
    cudaGetSymbolAddress(&hw_p,   g_hw);
    cudaGetSymbolAddress(&agg1_p, g_agg1);
    cudaGetSymbolAddress(&h2w_p,  g_h2w);

    constexpr int SMEM_M = (128 * (IN_CH + 4) + IN_CH * HIDDEN) * sizeof(float); // 100352
    cudaFuncSetAttribute(merged_kernel<P_PREP>,  cudaFuncAttributeMaxDynamicSharedMemorySize, SMEM_M);
    cudaFuncSetAttribute(merged_kernel<P_DEG>,   cudaFuncAttributeMaxDynamicSharedMemorySize, SMEM_M);
    cudaFuncSetAttribute(merged_kernel<P_SCANA>, cudaFuncAttributeMaxDynamicSharedMemorySize, SMEM_M);
    cudaFuncSetAttribute(merged_kernel<P_SCANB>, cudaFuncAttributeMaxDynamicSharedMemorySize, SMEM_M);
    cudaFuncSetAttribute(merged_kernel<P_SCANC>, cudaFuncAttributeMaxDynamicSharedMemorySize, SMEM_M);
    cudaFuncSetAttribute(merged_kernel<P_FILL>,  cudaFuncAttributeMaxDynamicSharedMemorySize, SMEM_M);

    // gemm1 tile budget per merged launch (sums to N_TILES=782)
    constexpr int G_PREP = 48, G_DEG = 190, G_SA = 48, G_SB = 48, G_SC = 48;
    constexpr int G_FILL = N_TILES - (G_PREP + G_DEG + G_SA + G_SB + G_SC); // 400
    constexpr int O_PREP = 0;
    constexpr int O_DEG  = O_PREP + G_PREP;
    constexpr int O_SA   = O_DEG + G_DEG;
    constexpr int O_SB   = O_SA + G_SA;
    constexpr int O_SC   = O_SB + G_SB;
    constexpr int O_FILL = O_SC + G_SC;

    const int nb_nodes = (N_NODES + 255) / 256;
    float* hw = (float*)hw_p;

    merged_kernel<P_PREP> <<<G_PREP + nb_nodes, 256, SMEM_M>>>(x, W1, hw, ei, G_PREP, O_PREP);
    merged_kernel<P_DEG>  <<<G_DEG  + NB_DEG,   256, SMEM_M>>>(x, W1, hw, ei, G_DEG,  O_DEG);
    merged_kernel<P_SCANA><<<G_SA   + SCAN_NB,  256, SMEM_M>>>(x, W1, hw, ei, G_SA,   O_SA);
    merged_kernel<P_SCANB><<<G_SB   + 1,        256, SMEM_M>>>(x, W1, hw, ei, G_SB,   O_SB);
    merged_kernel<P_SCANC><<<G_SC   + SCAN_NB,  256, SMEM_M>>>(x, W1, hw, ei, G_SC,   O_SC);
    merged_kernel<P_FILL> <<<G_FILL + NB_DEG,   256, SMEM_M>>>(x, W1, hw, ei, G_FILL, O_FILL);

    constexpr int TPB = 256;
    const int nb_warps = (N_NODES * 32 + TPB - 1) / TPB;  // 1 warp per node
    aggregate_kernel<HIDDEN><<<nb_warps, TPB>>>(hw, b1, (float*)agg1_p);

    constexpr int SMEM2 = (128 * (HIDDEN + 4) + HIDDEN * NCLS) * sizeof(float); // 45056
    cudaFuncSetAttribute(gemm2_kernel<HIDDEN, NCLS, 128>,
                         cudaFuncAttributeMaxDynamicSharedMemorySize, SMEM2);
    gemm2_kernel<HIDDEN, NCLS, 128>
        <<<(N_NODES + 127) / 128, (NCLS / 8) * 32, SMEM2>>>((const float*)agg1_p, W2,
                                                            (float*)h2w_p, N_NODES);

    aggregate_kernel<NCLS><<<nb_warps, TPB>>>((const float*)h2w_p, b2, out);
}